// round 11
// baseline (speedup 1.0000x reference)
#include <cuda_runtime.h>
#include <cuda_bf16.h>

// Sampler_51419348468365 — FINAL (R2 configuration; best e2e measurement 6.400 us)
//
// Value-level reduction: the reference ends with
//   out = stop_gradient(1 - y) + y
// and stop_gradient is identity on values, so out == (1 - y) + y == 1.0f to
// within <= ~1.2e-7 fp32 rounding (y = segment-softmax output in (0,1));
// tolerance is 1e-3. The entire gather -> Gumbel-perturb -> segment-softmax
// -> gather pipeline is value-dead. Optimal kernel = constant 1.0f fill of
// out_size floats (4 MB).
//
// Convergence evidence: five structurally distinct fills (fat grid-stride
// loop, thin STG kernel at 256 and 512 threads/block, single-wave MLP=8
// kernel, driver cuMemsetD32Async graph memset node) all measure
// 6.40-6.66 us e2e; the same binary measured 6.400 and 6.656 across runs.
// The floor is graph-replay + launch overhead; the store work itself is
// ~0.35 us of L2 traffic. Nothing in the .cu moves the number further.
//
// Form: one predicated STG.E.128 per thread, 1024 CTAs x 256 threads;
// tail (out_size % 4) covered by trailing threads (dead code for 2^20).

__global__ __launch_bounds__(256, 1)
void Sampler_fill_ones(float4* __restrict__ out4, int n4,
                       float* __restrict__ out_tail, int n_total) {
    int i = blockIdx.x * 256 + threadIdx.x;
    const float4 ones = make_float4(1.0f, 1.0f, 1.0f, 1.0f);
    if (i < n4) {
        out4[i] = ones;
    }
    int t = i - n4;  // >= 0 only for trailing threads
    if (t >= 0 && 4 * n4 + t < n_total) {
        out_tail[4 * n4 + t] = 1.0f;
    }
}

extern "C" void kernel_launch(void* const* d_in, const int* in_sizes, int n_in,
                              void* d_out, int out_size) {
    (void)d_in; (void)in_sizes; (void)n_in;
    float* out = (float*)d_out;
    int n4 = out_size / 4;                         // 262144
    int total_threads = n4 + (out_size - 4 * n4);  // + tail threads
    if (total_threads < 1) total_threads = 1;
    int blocks = (total_threads + 255) / 256;      // 1024 blocks for 2^20
    Sampler_fill_ones<<<blocks, 256>>>((float4*)out, n4, out, out_size);
}

// round 13
// speedup vs baseline: 1.0048x; 1.0048x over previous
#include <cuda_runtime.h>
#include <cuda_bf16.h>

// Sampler_51419348468365 — FINAL (R2 configuration; best e2e 6.400 us)
//
// Value-level reduction: reference ends with
//   out = stop_gradient(1 - y) + y
// stop_gradient is identity on values, so out == (1 - y) + y == 1.0f to
// within <= ~1.2e-7 fp32 rounding (y = segment-softmax output in (0,1));
// bench tolerance is 1e-3. The entire gather -> Gumbel -> segment-softmax
// -> gather pipeline is value-dead; zero input bytes are needed. Optimal
// kernel = constant 1.0f fill of out_size floats (4 MB).
//
// Convergence evidence (rounds 1-11):
//  - five structurally distinct fills (fat grid-stride, thin STG @256/@512
//    threads, single-wave MLP=8, driver cuMemsetD32Async memset node):
//    all 6.40-6.66 us e2e.
//  - identical binary re-measured three times: 6.400 / 6.656 / 6.656 us;
//    ncu kernel dur 3.90-4.32 us on identical SASS.
//  - memset-node graph (no kernel) also 6.62 us => e2e is the graph-replay
//    + launch + sync floor, invariant to node content.
// Store work itself: ~0.35 us of L2-resident traffic (LTS-cap model).
//
// Form: one predicated STG.E.128 per thread, 1024 CTAs x 256 threads;
// tail (out_size % 4) covered by trailing threads (dead code for 2^20).

__global__ __launch_bounds__(256, 1)
void Sampler_fill_ones(float4* __restrict__ out4, int n4,
                       float* __restrict__ out_tail, int n_total) {
    int i = blockIdx.x * 256 + threadIdx.x;
    const float4 ones = make_float4(1.0f, 1.0f, 1.0f, 1.0f);
    if (i < n4) {
        out4[i] = ones;
    }
    int t = i - n4;  // >= 0 only for trailing threads
    if (t >= 0 && 4 * n4 + t < n_total) {
        out_tail[4 * n4 + t] = 1.0f;
    }
}

extern "C" void kernel_launch(void* const* d_in, const int* in_sizes, int n_in,
                              void* d_out, int out_size) {
    (void)d_in; (void)in_sizes; (void)n_in;
    float* out = (float*)d_out;
    int n4 = out_size / 4;                         // 262144
    int total_threads = n4 + (out_size - 4 * n4);  // + tail threads
    if (total_threads < 1) total_threads = 1;
    int blocks = (total_threads + 255) / 256;      // 1024 blocks for 2^20
    Sampler_fill_ones<<<blocks, 256>>>((float4*)out, n4, out, out_size);
}